// round 16
// baseline (speedup 1.0000x reference)
#include <cuda_runtime.h>
#include <cstdint>
#include <math.h>

// Problem constants
#define Bq 16
#define Nq 4096
#define Cq 81
#define MAXPC 4096   // capacity per (b,c); also per-image kept capacity
#define KK 200       // per-class cap and final output count
#define NW 7         // ceil(200/32) words for keep/suppress bitmasks
#define ROWS_PB 128  // rois per argmax block
#define SLOWS 512    // smem sort capacity in per-class slow path
#define FCAP 2048    // finalize smem sort capacity

typedef unsigned long long u64;

// ---------------- device scratch (allocation-free rule: __device__ globals) ----------------
// Counters start zeroed (static init) and are re-zeroed by their consumers each run.
__device__ int   g_cnt[Bq * Cq];
__device__ float g_cscore[(size_t)Bq * Cq * MAXPC];
__device__ int   g_cidx[(size_t)Bq * Cq * MAXPC];
__device__ int   g_kcnt[Bq];
__device__ float g_kscore[Bq * MAXPC];
__device__ float g_kbox[Bq * MAXPC * 4];
__device__ int   g_ktag[Bq * MAXPC];                 // tag = class*4096 + roi_idx (<2^19)

// ---------------- kernel 1: staged per-roi argmax + emit (R4-exact; 9.2us measured) --------
// Softmax: p>0.5 implies argmax; reference emits iff argmax class != 0 and p > 0.5.
__global__ void __launch_bounds__(ROWS_PB) argmax_emit_kernel(const float* __restrict__ probs) {
    __shared__ float srow[ROWS_PB * Cq];   // 41472 B

    int tid = threadIdx.x;
    const float4* __restrict__ src = (const float4*)(probs + (size_t)blockIdx.x * ROWS_PB * Cq);
    float4* dst = (float4*)srow;
    #pragma unroll
    for (int i = 0; i < 20; i++)
        dst[i * ROWS_PB + tid] = src[i * ROWS_PB + tid];
    if (tid < 32) dst[20 * ROWS_PB + tid] = src[20 * ROWS_PB + tid];   // 2592 = 20*128+32
    __syncthreads();

    const float* r = srow + tid * Cq;
    float va = r[0]; int ia = 0;
    #pragma unroll
    for (int k = 1; k <= 40; k++) {
        float pv = r[k];
        if (pv > va) { va = pv; ia = k; }            // strict > keeps lowest index
    }
    float vb = r[41]; int ib = 41;
    #pragma unroll
    for (int k = 42; k < Cq; k++) {
        float pv = r[k];
        if (pv > vb) { vb = pv; ib = k; }
    }
    float v = va; int ix = ia;
    if (vb > va) { v = vb; ix = ib; }

    if (ix != 0 && v > 0.5f) {
        int g = blockIdx.x * ROWS_PB + tid;
        int b = g >> 12, n = g & (Nq - 1);
        int bc = b * Cq + ix;
        int pos = atomicAdd(&g_cnt[bc], 1);
        if (pos < MAXPC) {
            g_cscore[(size_t)bc * MAXPC + pos] = v;
            g_cidx[(size_t)bc * MAXPC + pos]   = n;
        }
    }
}

// ---------------- box decode ----------------
__device__ __forceinline__ void decode_box(const float* __restrict__ roi,
                                           const float* __restrict__ deltas,
                                           int b, int c, int idx,
                                           float& oy1, float& ox1, float& oy2, float& ox2) {
    const float* r = roi + ((size_t)b * Nq + idx) * 4;
    float y1 = r[0], x1 = r[1], y2 = r[2], x2 = r[3];
    float ah = y2 - y1, aw = x2 - x1;
    float acy = y1 + 0.5f * ah, acx = x1 + 0.5f * aw;
    const float* d = deltas + (((size_t)b * Nq + idx) * Cq + c) * 4;
    float dy = d[0] * 0.1f, dx = d[1] * 0.1f;
    float dh = d[2] * 0.2f, dw = d[3] * 0.2f;
    float bh = expf(dh) * ah, bw = expf(dw) * aw;
    float bcy = dy * ah + acy, bcx = dx * aw + acx;
    oy1 = bcy - 0.5f * bh; ox1 = bcx - 0.5f * bw;
    oy2 = oy1 + bh;        ox2 = ox1 + bw;
}

// ---------------- kernel 2: per-(b,c) NMS, ONE WARP per block (32 threads) ----------------
__global__ void __launch_bounds__(32) per_class_nms_kernel(const float* __restrict__ roi,
                                                           const float* __restrict__ deltas) {
    __shared__ u64 skey[SLOWS];                    // 4 KB (slow path only)
    __shared__ float sbox[KK * 4];                 // 3.2 KB
    __shared__ unsigned smask[KK * NW];            // 5.6 KB
    __shared__ unsigned skeep[NW];

    const unsigned FULL = 0xffffffffu;
    int bc = blockIdx.x;
    int b = bc / Cq, c = bc % Cq;
    int lane = threadIdx.x;
    int M = g_cnt[bc];                             // warp-uniform load
    if (M > MAXPC) M = MAXPC;
    if (M == 0) return;
    if (lane == 0) g_cnt[bc] = 0;                  // reset for next graph replay

    // =============== FAST PATH: M <= 32, fully register-resident ===============
    if (M <= 32) {
        u64 key = 0ull;
        if (lane < M) {
            float sc = g_cscore[(size_t)bc * MAXPC + lane];
            int   idx = g_cidx[(size_t)bc * MAXPC + lane];
            key = ((u64)__float_as_uint(sc) << 32) | (unsigned)(Nq - 1 - idx);
        }
        // in-register bitonic sort, descending (padding keys 0 sink to the end);
        // tie -> lower roi index first (matches lax.top_k stability)
        #pragma unroll
        for (int k = 2; k <= 32; k <<= 1) {
            #pragma unroll
            for (int j = k >> 1; j > 0; j >>= 1) {
                u64 other = __shfl_xor_sync(FULL, key, j);
                bool up = ((lane & j) == 0);
                bool desc = ((lane & k) == 0);
                u64 mx = key > other ? key : other;
                u64 mn = key > other ? other : key;
                key = (desc == up) ? mx : mn;
            }
        }
        int M2 = M;                                // <= 32 <= KK

        float by1 = 0.f, bxx1 = 0.f, by2 = 0.f, bxx2 = 0.f, area = 0.f;
        if (lane < M2) {
            int idx = Nq - 1 - (int)(key & 0xFFFFFFFFull);
            decode_box(roi, deltas, b, c, idx, by1, bxx1, by2, bxx2);
            area = fmaxf(by2 - by1, 0.0f) * fmaxf(bxx2 - bxx1, 0.0f);
        }
        // greedy NMS: shfl-broadcast box i, ballot suppressions (keep warp-uniform)
        unsigned keep = (M2 >= 32) ? FULL : ((1u << M2) - 1u);
        for (int i = 0; i < M2 - 1; i++) {
            if ((keep >> i) & 1u) {
                float iy1 = __shfl_sync(FULL, by1, i);
                float ix1 = __shfl_sync(FULL, bxx1, i);
                float iy2 = __shfl_sync(FULL, by2, i);
                float ix2 = __shfl_sync(FULL, bxx2, i);
                float ia  = __shfl_sync(FULL, area, i);
                float yy1 = fmaxf(iy1, by1), xx1 = fmaxf(ix1, bxx1);
                float yy2 = fminf(iy2, by2), xx2 = fminf(ix2, bxx2);
                float inter = fmaxf(yy2 - yy1, 0.0f) * fmaxf(xx2 - xx1, 0.0f);
                float iou = inter / (ia + area - inter + 1e-8f);
                unsigned sup = __ballot_sync(FULL,
                    (lane > i) && (lane < M2) && ((keep >> lane) & 1u) && (iou > 0.5f));
                keep &= ~sup;
            }
        }
        int nk = __popc(keep);
        int base = 0;
        if (lane == 0) base = atomicAdd(&g_kcnt[b], nk);
        base = __shfl_sync(FULL, base, 0);
        if ((lane < M2) && ((keep >> lane) & 1u)) {
            int pos = __popc(keep & ((lane == 0) ? 0u : ((1u << lane) - 1u)));
            int o = base + pos;
            int idx = Nq - 1 - (int)(key & 0xFFFFFFFFull);
            g_kscore[b * MAXPC + o] = __uint_as_float((unsigned)(key >> 32));
            g_ktag[b * MAXPC + o]   = c * Nq + idx;
            g_kbox[(b * MAXPC + o) * 4 + 0] = by1;
            g_kbox[(b * MAXPC + o) * 4 + 1] = bxx1;
            g_kbox[(b * MAXPC + o) * 4 + 2] = by2;
            g_kbox[(b * MAXPC + o) * 4 + 3] = bxx2;
        }
        return;
    }

    // =============== SLOW PATH: M > 32 (rare; single warp, R5-verified) ===============
    int S = 64;
    while (S < M) S <<= 1;
    bool in_smem = (S <= SLOWS);

    if (in_smem) {
        for (int i = lane; i < S; i += 32) {
            u64 key = 0ull;
            if (i < M) {
                float sc = g_cscore[(size_t)bc * MAXPC + i];
                int   idx = g_cidx[(size_t)bc * MAXPC + i];
                key = ((u64)__float_as_uint(sc) << 32) | (unsigned)(Nq - 1 - idx);
            }
            skey[i] = key;
        }
        __syncwarp();
        for (int k = 2; k <= S; k <<= 1)
            for (int j = k >> 1; j > 0; j >>= 1) {
                for (int i = lane; i < S; i += 32) {
                    int ixj = i ^ j;
                    if (ixj > i) {
                        u64 a = skey[i], bv = skey[ixj];
                        bool sw = ((i & k) == 0) ? (a < bv) : (a > bv);
                        if (sw) { skey[i] = bv; skey[ixj] = a; }
                    }
                }
                __syncwarp();
            }
    } else {
        // pad + bitonic-sort the global arrays in place (capacity MAXPC; extremely rare)
        for (int i = M + lane; i < S; i += 32) {
            g_cscore[(size_t)bc * MAXPC + i] = 0.0f;
            g_cidx[(size_t)bc * MAXPC + i]   = Nq - 1;
        }
        __syncwarp(); __threadfence_block();
        for (int k = 2; k <= S; k <<= 1)
            for (int j = k >> 1; j > 0; j >>= 1) {
                for (int i = lane; i < S; i += 32) {
                    int ixj = i ^ j;
                    if (ixj > i) {
                        float sa = g_cscore[(size_t)bc * MAXPC + i];
                        float sb = g_cscore[(size_t)bc * MAXPC + ixj];
                        int ida = g_cidx[(size_t)bc * MAXPC + i];
                        int idb = g_cidx[(size_t)bc * MAXPC + ixj];
                        u64 a  = ((u64)__float_as_uint(sa) << 32) | (unsigned)(Nq - 1 - ida);
                        u64 bv = ((u64)__float_as_uint(sb) << 32) | (unsigned)(Nq - 1 - idb);
                        bool sw = ((i & k) == 0) ? (a < bv) : (a > bv);
                        if (sw) {
                            g_cscore[(size_t)bc * MAXPC + i]   = sb;
                            g_cscore[(size_t)bc * MAXPC + ixj] = sa;
                            g_cidx[(size_t)bc * MAXPC + i]     = idb;
                            g_cidx[(size_t)bc * MAXPC + ixj]   = ida;
                        }
                    }
                }
                __syncwarp(); __threadfence_block();
            }
    }

    int M2 = (M < KK) ? M : KK;                    // reference per-class top-K cap

    for (int t = lane; t < M2 * NW; t += 32) smask[t] = 0u;
    for (int t = lane; t < M2; t += 32) {
        int idx = in_smem ? (Nq - 1 - (int)(skey[t] & 0xFFFFFFFFull))
                          : g_cidx[(size_t)bc * MAXPC + t];
        float oy1, ox1, oy2, ox2;
        decode_box(roi, deltas, b, c, idx, oy1, ox1, oy2, ox2);
        sbox[t * 4 + 0] = oy1;
        sbox[t * 4 + 1] = ox1;
        sbox[t * 4 + 2] = oy2;
        sbox[t * 4 + 3] = ox2;
    }
    __syncwarp();

    int npairs = M2 * M2;
    for (int t = lane; t < npairs; t += 32) {
        int i = t / M2, j = t % M2;
        if (j > i) {
            float iy1 = sbox[i * 4 + 0], ix1 = sbox[i * 4 + 1];
            float iy2 = sbox[i * 4 + 2], ix2 = sbox[i * 4 + 3];
            float jy1 = sbox[j * 4 + 0], jx1 = sbox[j * 4 + 1];
            float jy2 = sbox[j * 4 + 2], jx2 = sbox[j * 4 + 3];
            float yy1 = fmaxf(iy1, jy1), xx1 = fmaxf(ix1, jx1);
            float yy2 = fminf(iy2, jy2), xx2 = fminf(ix2, jx2);
            float inter = fmaxf(yy2 - yy1, 0.0f) * fmaxf(xx2 - xx1, 0.0f);
            float ia = fmaxf(iy2 - iy1, 0.0f) * fmaxf(ix2 - ix1, 0.0f);
            float ja = fmaxf(jy2 - jy1, 0.0f) * fmaxf(jx2 - jx1, 0.0f);
            float iou = inter / (ia + ja - inter + 1e-8f);
            if (iou > 0.5f)
                atomicOr(&smask[i * NW + (j >> 5)], 1u << (j & 31));
        }
    }
    __syncwarp();

    {
        int w = lane;
        unsigned kw = 0u;
        if (w < NW) {
            int lo = w * 32, nb = M2 - lo;
            kw = (nb >= 32) ? 0xFFFFFFFFu : (nb <= 0 ? 0u : ((1u << nb) - 1u));
        }
        for (int i = 0; i < M2; i++) {
            unsigned ow = __shfl_sync(FULL, kw, i >> 5);
            if ((ow >> (i & 31)) & 1u) {
                if (w < NW) kw &= ~smask[i * NW + w];
            }
        }
        if (w < NW) skeep[w] = kw;
    }
    __syncwarp();

    int nk = 0;
    for (int w = 0; w < NW; w++) nk += __popc(skeep[w]);
    int base = 0;
    if (lane == 0) base = atomicAdd(&g_kcnt[b], nk);
    base = __shfl_sync(FULL, base, 0);

    for (int t = lane; t < M2; t += 32) {
        int tw = t >> 5, tb = t & 31;
        if ((skeep[tw] >> tb) & 1u) {
            int pos = 0;
            for (int w = 0; w < tw; w++) pos += __popc(skeep[w]);
            pos += __popc(skeep[tw] & ((tb == 0) ? 0u : ((1u << tb) - 1u)));
            int o = base + pos;
            int idx; float sc;
            if (in_smem) {
                u64 key = skey[t];
                idx = Nq - 1 - (int)(key & 0xFFFFFFFFull);
                sc  = __uint_as_float((unsigned)(key >> 32));
            } else {
                idx = g_cidx[(size_t)bc * MAXPC + t];
                sc  = g_cscore[(size_t)bc * MAXPC + t];
            }
            g_kscore[b * MAXPC + o] = sc;
            g_ktag[b * MAXPC + o]   = c * Nq + idx;
            g_kbox[(b * MAXPC + o) * 4 + 0] = sbox[t * 4 + 0];
            g_kbox[(b * MAXPC + o) * 4 + 1] = sbox[t * 4 + 1];
            g_kbox[(b * MAXPC + o) * 4 + 2] = sbox[t * 4 + 2];
            g_kbox[(b * MAXPC + o) * 4 + 3] = sbox[t * 4 + 3];
        }
    }
}

// ---------------- kernel 3: per-image top-200 via two-level radix select + tiny sort -------
__device__ __forceinline__ unsigned score_dd(unsigned bits) {
    unsigned d = bits - 0x3F000000u;     // (0, 0x800000] for scores in (0.5, 1.0]
    return d > 0x7FFFFFu ? 0x7FFFFFu : d;
}

__global__ void __launch_bounds__(1024) finalize_kernel(float* __restrict__ out) {
    __shared__ u64 skey[FCAP];   // 16 KB
    __shared__ int hist[256];
    __shared__ int s_cnt, s_bsel, s_need2, s_bsel2;

    int b = blockIdx.x;
    int tid = threadIdx.x;
    int Mi = g_kcnt[b];
    if (Mi > MAXPC) Mi = MAXPC;
    int target = Mi < KK ? Mi : KK;

    if (tid < 256) hist[tid] = 0;
    if (tid == 0) { s_cnt = 0; g_kcnt[b] = 0; }    // reset for next graph replay
    __syncthreads();

    // level-1 histogram: top 8 bits of mantissa-delta (scores in (0.5,1.0])
    for (int i = tid; i < Mi; i += blockDim.x) {
        unsigned dd = score_dd(__float_as_uint(g_kscore[b * MAXPC + i]));
        atomicAdd(&hist[dd >> 15], 1);
    }
    __syncthreads();

    if (tid == 0) {
        int cum = 0, bsel = 0;
        s_need2 = 0;
        for (int bk = 255; bk >= 0; bk--) {
            cum += hist[bk];
            if (cum >= target) { bsel = bk; s_need2 = target - (cum - hist[bk]); break; }
        }
        s_bsel = bsel;
    }
    __syncthreads();
    int bsel = s_bsel, need2 = s_need2;

    // level-2 refine within the cutoff bucket (next 8 mantissa bits)
    if (tid < 256) hist[tid] = 0;
    __syncthreads();
    for (int i = tid; i < Mi; i += blockDim.x) {
        unsigned dd = score_dd(__float_as_uint(g_kscore[b * MAXPC + i]));
        if ((int)(dd >> 15) == bsel)
            atomicAdd(&hist[(dd >> 7) & 0xFF], 1);
    }
    __syncthreads();

    if (tid == 0) {
        int cum = 0, bsel2 = 0;
        for (int bk = 255; bk >= 0; bk--) {
            cum += hist[bk];
            if (cum >= need2) { bsel2 = bk; break; }
        }
        s_bsel2 = bsel2;
    }
    __syncthreads();
    int bsel2 = s_bsel2;

    // compact keys above the refined cutoff (score desc; tie -> class asc, roi asc via
    // inverted tag; low 12 bits carry the storage slot as payload)
    for (int i = tid; i < Mi; i += blockDim.x) {
        unsigned bits = __float_as_uint(g_kscore[b * MAXPC + i]);
        unsigned dd = score_dd(bits);
        int l1 = (int)(dd >> 15);
        bool take = (l1 > bsel) || (l1 == bsel && (int)((dd >> 7) & 0xFF) >= bsel2);
        if (take) {
            int pos = atomicAdd(&s_cnt, 1);
            if (pos < FCAP) {
                int tag = g_ktag[b * MAXPC + i];
                skey[pos] = ((u64)bits << 32) |
                            ((u64)((0xFFFFFu - (unsigned)tag) & 0xFFFFFu) << 12) |
                            (u64)(unsigned)i;
            }
        }
    }
    __syncthreads();
    int cnt = s_cnt < FCAP ? s_cnt : FCAP;         // ~target + ties (128-ulp window)

    int S = 0;
    if (cnt > 0) { S = 32; while (S < cnt) S <<= 1; }
    for (int i = cnt + tid; i < S; i += blockDim.x) skey[i] = 0ull;
    __syncthreads();

    for (int k = 2; k <= S; k <<= 1) {
        for (int j = k >> 1; j > 0; j >>= 1) {
            for (int i = tid; i < S; i += blockDim.x) {
                int ixj = i ^ j;
                if (ixj > i) {
                    u64 a = skey[i], bv = skey[ixj];
                    bool sw = ((i & k) == 0) ? (a < bv) : (a > bv);
                    if (sw) { skey[i] = bv; skey[ixj] = a; }
                }
            }
            __syncthreads();
        }
    }

    // write top-200 (boxes, labels, scores), zero-padding: covers 100% of d_out
    int vlim = cnt < target ? cnt : target;
    for (int t = tid; t < KK; t += blockDim.x) {
        float bx0 = 0.f, bx1 = 0.f, bx2 = 0.f, bx3 = 0.f, lbl = 0.f, scv = 0.f;
        if (t < vlim) {
            u64 key = skey[t];
            scv = __uint_as_float((unsigned)(key >> 32));   // always > 0.5 here
            int slot = (int)(key & 0xFFFull);
            int tag = 0xFFFFF - (int)((key >> 12) & 0xFFFFFull);
            lbl = (float)(tag >> 12);                       // tag / 4096 = class
            const float* bp = &g_kbox[(b * MAXPC + slot) * 4];
            bx0 = fminf(fmaxf(bp[0], 0.0f), 1.0f);
            bx1 = fminf(fmaxf(bp[1], 0.0f), 1.0f);
            bx2 = fminf(fmaxf(bp[2], 0.0f), 1.0f);
            bx3 = fminf(fmaxf(bp[3], 0.0f), 1.0f);
        }
        float* ob = out + ((size_t)b * KK + t) * 4;
        ob[0] = bx0; ob[1] = bx1; ob[2] = bx2; ob[3] = bx3;
        out[(size_t)Bq * KK * 4 + (size_t)b * KK + t] = lbl;
        out[(size_t)Bq * KK * 4 + (size_t)Bq * KK + (size_t)b * KK + t] = scv;
    }
}

// ---------------- host launch ----------------
extern "C" void kernel_launch(void* const* d_in, const int* in_sizes, int n_in,
                              void* d_out, int out_size) {
    const float* roi = nullptr;     // B*N*4       = 262144
    const float* deltas = nullptr;  // B*N*C*4     = 21233664
    const float* probs = nullptr;   // B*N*C       = 5308416
    for (int i = 0; i < n_in; i++) {
        if (in_sizes[i] == Bq * Nq * 4)           roi    = (const float*)d_in[i];
        else if (in_sizes[i] == Bq * Nq * Cq * 4) deltas = (const float*)d_in[i];
        else if (in_sizes[i] == Bq * Nq * Cq)     probs  = (const float*)d_in[i];
    }
    float* out = (float*)d_out;

    argmax_emit_kernel<<<(Bq * Nq) / ROWS_PB, ROWS_PB>>>(probs);
    per_class_nms_kernel<<<Bq * Cq, 32>>>(roi, deltas);
    finalize_kernel<<<Bq, 1024>>>(out);
}

// round 17
// speedup vs baseline: 1.0739x; 1.0739x over previous
#include <cuda_runtime.h>
#include <cstdint>
#include <math.h>

// Problem constants
#define Bq 16
#define Nq 4096
#define Cq 81
#define MAXPC 4096   // capacity per (b,c); also per-image kept capacity
#define KK 200       // per-class cap and final output count
#define NW 7         // ceil(200/32) words for keep/suppress bitmasks
#define ROWS_PB 64   // rois per argmax block (20.7KB smem -> 8 blocks/SM)
#define FCAP 2048    // finalize smem sort capacity

typedef unsigned long long u64;

// ---------------- device scratch (allocation-free rule: __device__ globals) ----------------
// Counters start zeroed (static init) and are re-zeroed by their consumers each run.
__device__ int   g_cnt[Bq * Cq];
__device__ float g_cscore[(size_t)Bq * Cq * MAXPC];
__device__ int   g_cidx[(size_t)Bq * Cq * MAXPC];
__device__ int   g_kcnt[Bq];
__device__ float g_kscore[Bq * MAXPC];
__device__ float g_kbox[Bq * MAXPC * 4];
__device__ int   g_ktag[Bq * MAXPC];                 // tag = class*4096 + roi_idx (<2^19)

// ---------------- kernel 1: staged argmax, 64 rows/block, 4 threads/row ----------------
// Softmax: p>0.5 implies argmax; reference emits iff argmax class != 0 and p > 0.5.
// 20.7KB smem + 256 threads -> 8 blocks/SM (4x the old occupancy) so the coalesced
// staging loads of many blocks overlap; scan phase splits each row across 4 threads.
__global__ void __launch_bounds__(256) argmax_emit_kernel(const float* __restrict__ probs) {
    __shared__ float srow[ROWS_PB * Cq];   // 64*81*4 = 20736 B
    const unsigned FULL = 0xffffffffu;

    int tid = threadIdx.x;
    const float4* __restrict__ src = (const float4*)(probs + (size_t)blockIdx.x * ROWS_PB * Cq);
    float4* dst = (float4*)srow;
    // 64*81/4 = 1296 float4s = 5*256 + 16
    #pragma unroll
    for (int i = 0; i < 5; i++)
        dst[i * 256 + tid] = src[i * 256 + tid];
    if (tid < 16) dst[1280 + tid] = src[1280 + tid];
    __syncthreads();

    int row = tid >> 2, q = tid & 3;
    const float* r = srow + row * Cq;
    int k0 = q * 21;                                // quarters: 21/21/21/18
    float v = -1.0f; int ix = 0;
    #pragma unroll
    for (int k = 0; k < 21; k++) {
        int idx = k0 + k;
        float pv = (idx < Cq) ? r[idx] : -1.0f;
        if (pv > v) { v = pv; ix = idx; }           // strict > keeps lowest index
    }
    // merge the 4 quarters (groups of 4 lanes are shfl-aligned; sources carry larger
    // indices, so the generic lowest-index tie rule is exact)
    #pragma unroll
    for (int off = 2; off; off >>= 1) {
        float ov = __shfl_down_sync(FULL, v, off);
        int   oi = __shfl_down_sync(FULL, ix, off);
        if ((q + off < 4) && (ov > v || (ov == v && oi < ix))) { v = ov; ix = oi; }
    }

    if (q == 0 && ix != 0 && v > 0.5f) {
        int g = blockIdx.x * ROWS_PB + row;         // blocks never straddle images (4096%64==0)
        int b = g >> 12, n = g & (Nq - 1);
        int bc = b * Cq + ix;
        int pos = atomicAdd(&g_cnt[bc], 1);
        if (pos < MAXPC) {
            g_cscore[(size_t)bc * MAXPC + pos] = v;
            g_cidx[(size_t)bc * MAXPC + pos]   = n;
        }
    }
}

// ---------------- kernel 2: per-(b,c) sort + cap-200 + bitmask greedy NMS (R4-exact) --------
__global__ void per_class_nms_kernel(const float* __restrict__ roi,
                                     const float* __restrict__ deltas) {
    __shared__ u64 skey[MAXPC];                    // 32 KB
    __shared__ float sbox[KK * 4];
    __shared__ unsigned smask[KK * NW];            // suppression bit-matrix: row i = boxes i kills
    __shared__ unsigned skeep[NW];                 // final keep mask
    __shared__ int   s_base;

    int bc = blockIdx.x;
    int b = bc / Cq, c = bc % Cq;
    int M = g_cnt[bc];                             // every thread reads M before it is re-zeroed
    if (M > MAXPC) M = MAXPC;
    if (M == 0) return;                            // counter already 0

    int S = 32;
    while (S < M) S <<= 1;

    // key: score bits desc, tie -> lower roi index first (matches lax.top_k stability)
    for (int i = threadIdx.x; i < S; i += blockDim.x) {
        u64 key = 0ull;
        if (i < M) {
            float sc = g_cscore[(size_t)bc * MAXPC + i];
            int   idx = g_cidx[(size_t)bc * MAXPC + i];
            key = ((u64)__float_as_uint(sc) << 32) | (unsigned)(Nq - 1 - idx);
        }
        skey[i] = key;
    }
    __syncthreads();
    if (threadIdx.x == 0) g_cnt[bc] = 0;           // reset for next graph replay (post-barrier)

    for (int k = 2; k <= S; k <<= 1) {
        for (int j = k >> 1; j > 0; j >>= 1) {
            for (int i = threadIdx.x; i < S; i += blockDim.x) {
                int ixj = i ^ j;
                if (ixj > i) {
                    u64 a = skey[i], bv = skey[ixj];
                    bool sw = ((i & k) == 0) ? (a < bv) : (a > bv);
                    if (sw) { skey[i] = bv; skey[ixj] = a; }
                }
            }
            __syncthreads();
        }
    }

    int M2 = (M < KK) ? M : KK;   // reference per-class top-K cap

    // decode boxes for the capped candidate set; zero the bitmask rows
    for (int t = threadIdx.x; t < M2 * NW; t += blockDim.x) smask[t] = 0u;
    for (int t = threadIdx.x; t < M2; t += blockDim.x) {
        int idx = Nq - 1 - (int)(skey[t] & 0xFFFFFFFFull);
        const float* r = roi + ((size_t)b * Nq + idx) * 4;
        float y1 = r[0], x1 = r[1], y2 = r[2], x2 = r[3];
        float ah = y2 - y1, aw = x2 - x1;
        float acy = y1 + 0.5f * ah, acx = x1 + 0.5f * aw;
        const float* d = deltas + (((size_t)b * Nq + idx) * Cq + c) * 4;
        float dy = d[0] * 0.1f, dx = d[1] * 0.1f;
        float dh = d[2] * 0.2f, dw = d[3] * 0.2f;
        float bh = expf(dh) * ah, bw = expf(dw) * aw;
        float bcy = dy * ah + acy, bcx = dx * aw + acx;
        float oy1 = bcy - 0.5f * bh, ox1 = bcx - 0.5f * bw;
        sbox[t * 4 + 0] = oy1;
        sbox[t * 4 + 1] = ox1;
        sbox[t * 4 + 2] = oy1 + bh;
        sbox[t * 4 + 3] = ox1 + bw;
    }
    __syncthreads();

    // parallel IoU bit-matrix over all (i,j>i) pairs — no serial sync loop
    int npairs = M2 * M2;
    for (int t = threadIdx.x; t < npairs; t += blockDim.x) {
        int i = t / M2, j = t % M2;
        if (j > i) {
            float iy1 = sbox[i * 4 + 0], ix1 = sbox[i * 4 + 1];
            float iy2 = sbox[i * 4 + 2], ix2 = sbox[i * 4 + 3];
            float jy1 = sbox[j * 4 + 0], jx1 = sbox[j * 4 + 1];
            float jy2 = sbox[j * 4 + 2], jx2 = sbox[j * 4 + 3];
            float yy1 = fmaxf(iy1, jy1), xx1 = fmaxf(ix1, jx1);
            float yy2 = fminf(iy2, jy2), xx2 = fminf(ix2, jx2);
            float inter = fmaxf(yy2 - yy1, 0.0f) * fmaxf(xx2 - xx1, 0.0f);
            float ia = fmaxf(iy2 - iy1, 0.0f) * fmaxf(ix2 - ix1, 0.0f);
            float ja = fmaxf(jy2 - jy1, 0.0f) * fmaxf(jx2 - jx1, 0.0f);
            float iou = inter / (ia + ja - inter + 1e-8f);
            if (iou > 0.5f)
                atomicOr(&smask[i * NW + (j >> 5)], 1u << (j & 31));
        }
    }
    __syncthreads();

    // greedy scan in ONE warp: keep mask lives in lanes 0..NW-1, decision bit via shfl
    if (threadIdx.x < 32) {
        int w = threadIdx.x;
        unsigned kw = 0u;
        if (w < NW) {
            int lo = w * 32;
            int nb = M2 - lo;
            kw = (nb >= 32) ? 0xFFFFFFFFu : (nb <= 0 ? 0u : ((1u << nb) - 1u));
        }
        for (int i = 0; i < M2; i++) {
            unsigned ow = __shfl_sync(0xffffffffu, kw, i >> 5);
            if ((ow >> (i & 31)) & 1u) {
                if (w < NW) kw &= ~smask[i * NW + w];   // rows only contain bits j>i
            }
        }
        if (w < NW) skeep[w] = kw;
    }
    __syncthreads();

    // popcount-based compaction into the per-image list
    if (threadIdx.x == 0) {
        int nk = 0;
        for (int w = 0; w < NW; w++) nk += __popc(skeep[w]);
        s_base = atomicAdd(&g_kcnt[b], nk);
    }
    __syncthreads();
    int base = s_base;
    for (int t = threadIdx.x; t < M2; t += blockDim.x) {
        int tw = t >> 5, tb = t & 31;
        if ((skeep[tw] >> tb) & 1u) {
            int pos = 0;
            for (int w = 0; w < tw; w++) pos += __popc(skeep[w]);
            pos += __popc(skeep[tw] & ((tb == 0) ? 0u : ((1u << tb) - 1u)));
            int o = base + pos;
            u64 key = skey[t];
            int idx = Nq - 1 - (int)(key & 0xFFFFFFFFull);
            g_kscore[b * MAXPC + o] = __uint_as_float((unsigned)(key >> 32));
            g_ktag[b * MAXPC + o]   = c * Nq + idx;
            g_kbox[(b * MAXPC + o) * 4 + 0] = sbox[t * 4 + 0];
            g_kbox[(b * MAXPC + o) * 4 + 1] = sbox[t * 4 + 1];
            g_kbox[(b * MAXPC + o) * 4 + 2] = sbox[t * 4 + 2];
            g_kbox[(b * MAXPC + o) * 4 + 3] = sbox[t * 4 + 3];
        }
    }
}

// ---------------- kernel 3: per-image top-200 via two-level radix select + tiny sort -------
__device__ __forceinline__ unsigned score_dd(unsigned bits) {
    unsigned d = bits - 0x3F000000u;     // (0, 0x800000] for scores in (0.5, 1.0]
    return d > 0x7FFFFFu ? 0x7FFFFFu : d;
}

__global__ void __launch_bounds__(1024) finalize_kernel(float* __restrict__ out) {
    __shared__ u64 skey[FCAP];   // 16 KB
    __shared__ int hist[256];
    __shared__ int s_cnt, s_bsel, s_need2, s_bsel2;

    int b = blockIdx.x;
    int tid = threadIdx.x;
    int Mi = g_kcnt[b];
    if (Mi > MAXPC) Mi = MAXPC;
    int target = Mi < KK ? Mi : KK;

    if (tid < 256) hist[tid] = 0;
    if (tid == 0) { s_cnt = 0; g_kcnt[b] = 0; }    // reset for next graph replay
    __syncthreads();

    // level-1 histogram: top 8 bits of mantissa-delta (scores in (0.5,1.0])
    for (int i = tid; i < Mi; i += blockDim.x) {
        unsigned dd = score_dd(__float_as_uint(g_kscore[b * MAXPC + i]));
        atomicAdd(&hist[dd >> 15], 1);
    }
    __syncthreads();

    if (tid == 0) {
        int cum = 0, bsel = 0;
        s_need2 = 0;
        for (int bk = 255; bk >= 0; bk--) {
            cum += hist[bk];
            if (cum >= target) { bsel = bk; s_need2 = target - (cum - hist[bk]); break; }
        }
        s_bsel = bsel;
    }
    __syncthreads();
    int bsel = s_bsel, need2 = s_need2;

    // level-2 refine within the cutoff bucket (next 8 mantissa bits)
    if (tid < 256) hist[tid] = 0;
    __syncthreads();
    for (int i = tid; i < Mi; i += blockDim.x) {
        unsigned dd = score_dd(__float_as_uint(g_kscore[b * MAXPC + i]));
        if ((int)(dd >> 15) == bsel)
            atomicAdd(&hist[(dd >> 7) & 0xFF], 1);
    }
    __syncthreads();

    if (tid == 0) {
        int cum = 0, bsel2 = 0;
        for (int bk = 255; bk >= 0; bk--) {
            cum += hist[bk];
            if (cum >= need2) { bsel2 = bk; break; }
        }
        s_bsel2 = bsel2;
    }
    __syncthreads();
    int bsel2 = s_bsel2;

    // compact keys above the refined cutoff (score desc; tie -> class asc, roi asc via
    // inverted tag; low 12 bits carry the storage slot as payload)
    for (int i = tid; i < Mi; i += blockDim.x) {
        unsigned bits = __float_as_uint(g_kscore[b * MAXPC + i]);
        unsigned dd = score_dd(bits);
        int l1 = (int)(dd >> 15);
        bool take = (l1 > bsel) || (l1 == bsel && (int)((dd >> 7) & 0xFF) >= bsel2);
        if (take) {
            int pos = atomicAdd(&s_cnt, 1);
            if (pos < FCAP) {
                int tag = g_ktag[b * MAXPC + i];
                skey[pos] = ((u64)bits << 32) |
                            ((u64)((0xFFFFFu - (unsigned)tag) & 0xFFFFFu) << 12) |
                            (u64)(unsigned)i;
            }
        }
    }
    __syncthreads();
    int cnt = s_cnt < FCAP ? s_cnt : FCAP;         // ~target + ties (128-ulp window)

    int S = 0;
    if (cnt > 0) { S = 32; while (S < cnt) S <<= 1; }
    for (int i = cnt + tid; i < S; i += blockDim.x) skey[i] = 0ull;
    __syncthreads();

    for (int k = 2; k <= S; k <<= 1) {
        for (int j = k >> 1; j > 0; j >>= 1) {
            for (int i = tid; i < S; i += blockDim.x) {
                int ixj = i ^ j;
                if (ixj > i) {
                    u64 a = skey[i], bv = skey[ixj];
                    bool sw = ((i & k) == 0) ? (a < bv) : (a > bv);
                    if (sw) { skey[i] = bv; skey[ixj] = a; }
                }
            }
            __syncthreads();
        }
    }

    // write top-200 (boxes, labels, scores), zero-padding: covers 100% of d_out
    int vlim = cnt < target ? cnt : target;
    for (int t = tid; t < KK; t += blockDim.x) {
        float bx0 = 0.f, bx1 = 0.f, bx2 = 0.f, bx3 = 0.f, lbl = 0.f, scv = 0.f;
        if (t < vlim) {
            u64 key = skey[t];
            scv = __uint_as_float((unsigned)(key >> 32));   // always > 0.5 here
            int slot = (int)(key & 0xFFFull);
            int tag = 0xFFFFF - (int)((key >> 12) & 0xFFFFFull);
            lbl = (float)(tag >> 12);                       // tag / 4096 = class
            const float* bp = &g_kbox[(b * MAXPC + slot) * 4];
            bx0 = fminf(fmaxf(bp[0], 0.0f), 1.0f);
            bx1 = fminf(fmaxf(bp[1], 0.0f), 1.0f);
            bx2 = fminf(fmaxf(bp[2], 0.0f), 1.0f);
            bx3 = fminf(fmaxf(bp[3], 0.0f), 1.0f);
        }
        float* ob = out + ((size_t)b * KK + t) * 4;
        ob[0] = bx0; ob[1] = bx1; ob[2] = bx2; ob[3] = bx3;
        out[(size_t)Bq * KK * 4 + (size_t)b * KK + t] = lbl;
        out[(size_t)Bq * KK * 4 + (size_t)Bq * KK + (size_t)b * KK + t] = scv;
    }
}

// ---------------- host launch ----------------
extern "C" void kernel_launch(void* const* d_in, const int* in_sizes, int n_in,
                              void* d_out, int out_size) {
    const float* roi = nullptr;     // B*N*4       = 262144
    const float* deltas = nullptr;  // B*N*C*4     = 21233664
    const float* probs = nullptr;   // B*N*C       = 5308416
    for (int i = 0; i < n_in; i++) {
        if (in_sizes[i] == Bq * Nq * 4)           roi    = (const float*)d_in[i];
        else if (in_sizes[i] == Bq * Nq * Cq * 4) deltas = (const float*)d_in[i];
        else if (in_sizes[i] == Bq * Nq * Cq)     probs  = (const float*)d_in[i];
    }
    float* out = (float*)d_out;

    argmax_emit_kernel<<<(Bq * Nq) / ROWS_PB, 256>>>(probs);
    per_class_nms_kernel<<<Bq * Cq, 256>>>(roi, deltas);
    finalize_kernel<<<Bq, 1024>>>(out);
}